// round 1
// baseline (speedup 1.0000x reference)
#include <cuda_runtime.h>
#include <cuda_bf16.h>
#include <math.h>

// Problem shapes (fixed by the reference)
#define B_  4
#define H_  12
#define S_  2048
#define D_  64
#define BH_ 48          // B_*H_
#define QT  128         // q rows per CTA
#define KT1 128         // k chunk, kernel 1
#define KT2 64          // k chunk, kernel 2

// Scratch: per-row softmax denominators l[bh][q]
__device__ float g_l[BH_ * S_];

// ---------------------------------------------------------------------------
// Kernel 1: e[q][k] = masked exp(Q.K^T / 8)  (unnormalized), l[q] = sum_k e
//   grid (16, 48), block 256. Thread (ty=tid/16, tx=tid%16), micro-tile 8x8
//   rows = ty + 16*i, cols = tx + 16*j  (strided -> conflict-free LDS.128)
// ---------------------------------------------------------------------------
__global__ void __launch_bounds__(256)
qk_scores_kernel(const float* __restrict__ Q, const float* __restrict__ K,
                 const int* __restrict__ mask, float* __restrict__ e_out)
{
    extern __shared__ float sm[];
    float* Qs  = sm;                    // 128 x 64      (8192 words)
    float* Ks  = Qs + QT * D_;          // 128 x 68      (8704 words, padded)
    float* red = Ks + KT1 * 68;         // 128 x 16      (2048 words)
    int*   mqs = (int*)(red + QT * 16); // 128
    int*   mks = mqs + QT;              // 128

    const int bh  = blockIdx.y;
    const int b   = bh / H_;
    const int q0  = blockIdx.x * QT;
    const int tid = threadIdx.x;
    const int tx  = tid & 15;
    const int ty  = tid >> 4;

    // Load Q tile (coalesced float4)
    {
        const float4* Qg  = (const float4*)(Q + (size_t)(bh * S_ + q0) * D_);
        float4*       Qs4 = (float4*)Qs;
#pragma unroll
        for (int i = 0; i < 8; ++i) {
            int r = ty + 16 * i;
            Qs4[r * 16 + tx] = Qg[r * 16 + tx];
        }
    }
    if (tid < QT) mqs[tid] = mask[b * S_ + q0 + tid];
    __syncthreads();

    float rs[8];
#pragma unroll
    for (int i = 0; i < 8; ++i) rs[i] = 0.0f;

    for (int kc = 0; kc < S_; kc += KT1) {
        // Load K chunk with padded stride 68 words (17 float4)
        {
            const float4* Kg  = (const float4*)(K + (size_t)(bh * S_ + kc) * D_);
            float4*       Ks4 = (float4*)Ks;
#pragma unroll
            for (int i = 0; i < 8; ++i) {
                int r = ty + 16 * i;
                Ks4[r * 17 + tx] = Kg[r * 16 + tx];
            }
        }
        if (tid < KT1) mks[tid] = mask[b * S_ + kc + tid];
        __syncthreads();

        float c[8][8];
#pragma unroll
        for (int i = 0; i < 8; ++i)
#pragma unroll
            for (int j = 0; j < 8; ++j) c[i][j] = 0.0f;

        const float4* Qs4 = (const float4*)Qs;
        const float4* Ks4 = (const float4*)Ks;
#pragma unroll 1
        for (int d4 = 0; d4 < 16; ++d4) {
            float4 a4[8], b4[8];
#pragma unroll
            for (int i = 0; i < 8; ++i) a4[i] = Qs4[(ty + 16 * i) * 16 + d4];
#pragma unroll
            for (int j = 0; j < 8; ++j) b4[j] = Ks4[(tx + 16 * j) * 17 + d4];
#pragma unroll
            for (int i = 0; i < 8; ++i)
#pragma unroll
                for (int j = 0; j < 8; ++j) {
                    c[i][j] = fmaf(a4[i].x, b4[j].x, c[i][j]);
                    c[i][j] = fmaf(a4[i].y, b4[j].y, c[i][j]);
                    c[i][j] = fmaf(a4[i].z, b4[j].z, c[i][j]);
                    c[i][j] = fmaf(a4[i].w, b4[j].w, c[i][j]);
                }
        }

        // Epilogue: mask + exp + store e + accumulate row sums
#pragma unroll
        for (int i = 0; i < 8; ++i) {
            const int qm = mqs[ty + 16 * i];
            float* erow = e_out + (size_t)(bh * S_ + q0 + ty + 16 * i) * S_ + kc;
            float acc = 0.0f;
#pragma unroll
            for (int j = 0; j < 8; ++j) {
                float ev;
                if (qm == 0)                    ev = 1.0f;            // fully masked row -> uniform
                else if (mks[tx + 16 * j] == 0) ev = 0.0f;            // masked key
                else                            ev = __expf(c[i][j] * 0.125f);
                acc += ev;
                erow[tx + 16 * j] = ev;
            }
            rs[i] += acc;
        }
        __syncthreads();
    }

    // Deterministic row-sum reduction (no fp atomics)
#pragma unroll
    for (int i = 0; i < 8; ++i) red[(ty + 16 * i) * 16 + tx] = rs[i];
    __syncthreads();
    if (tid < QT) {
        float l = 0.0f;
#pragma unroll
        for (int t = 0; t < 16; ++t) l += red[tid * 16 + t];
        g_l[bh * S_ + q0 + tid] = l;
    }
}

// ---------------------------------------------------------------------------
// Kernel 2: p = e / l (written back to p_attn), out = p @ V
//   grid (16, 48), block 256. Micro-tile 8 rows x 4 d-cols.
// ---------------------------------------------------------------------------
__global__ void __launch_bounds__(256, 2)
pv_kernel(const float* __restrict__ V, float* __restrict__ p,
          float* __restrict__ out)
{
    extern __shared__ float sm[];
    float* As  = sm;                 // 128 x 64  (scaled p tile)      8192 words
    float* Bst = As + QT * D_;       // 64(d) x 68(k, padded)          4352 words
    float* rl  = Bst + D_ * 68;      // 128 reciprocal row sums

    const int bh  = blockIdx.y;
    const int q0  = blockIdx.x * QT;
    const int tid = threadIdx.x;
    const int tx  = tid & 15;
    const int ty  = tid >> 4;

    if (tid < QT) rl[tid] = 1.0f / g_l[bh * S_ + q0 + tid];
    __syncthreads();

    float c[8][4];
#pragma unroll
    for (int i = 0; i < 8; ++i)
#pragma unroll
        for (int j = 0; j < 4; ++j) c[i][j] = 0.0f;

    for (int kc = 0; kc < S_; kc += KT2) {
        // Stage A: read e, scale by 1/l, write normalized p, keep in smem
        {
            float4* As4 = (float4*)As;
#pragma unroll
            for (int i = 0; i < 8; ++i) {
                int row = ty + 16 * i;
                size_t off = (size_t)(bh * S_ + q0 + row) * S_ + kc + tx * 4;
                float4 ev = *(const float4*)(p + off);
                float rc = rl[row];
                ev.x *= rc; ev.y *= rc; ev.z *= rc; ev.w *= rc;
                *(float4*)(p + off) = ev;
                As4[row * 16 + tx] = ev;
            }
        }
        // Stage B: V chunk transposed -> Bst[d][kk], stride 68 words
        for (int t = tid; t < 64 * 16; t += 256) {
            int row = t >> 4;      // kk in chunk
            int d4  = t & 15;
            float4 v4 = *(const float4*)(V + (size_t)(bh * S_ + kc + row) * D_ + d4 * 4);
            Bst[(d4 * 4 + 0) * 68 + row] = v4.x;
            Bst[(d4 * 4 + 1) * 68 + row] = v4.y;
            Bst[(d4 * 4 + 2) * 68 + row] = v4.z;
            Bst[(d4 * 4 + 3) * 68 + row] = v4.w;
        }
        __syncthreads();

        const float4* As4  = (const float4*)As;
        const float4* Bst4 = (const float4*)Bst;
#pragma unroll 1
        for (int k4 = 0; k4 < 16; ++k4) {
            float4 a4[8], b4[4];
#pragma unroll
            for (int i = 0; i < 8; ++i) a4[i] = As4[(ty + 16 * i) * 16 + k4];
#pragma unroll
            for (int j = 0; j < 4; ++j) b4[j] = Bst4[(tx + 16 * j) * 17 + k4];
#pragma unroll
            for (int i = 0; i < 8; ++i)
#pragma unroll
                for (int j = 0; j < 4; ++j) {
                    c[i][j] = fmaf(a4[i].x, b4[j].x, c[i][j]);
                    c[i][j] = fmaf(a4[i].y, b4[j].y, c[i][j]);
                    c[i][j] = fmaf(a4[i].z, b4[j].z, c[i][j]);
                    c[i][j] = fmaf(a4[i].w, b4[j].w, c[i][j]);
                }
        }
        __syncthreads();
    }

    // Write O
#pragma unroll
    for (int i = 0; i < 8; ++i) {
        float* orow = out + (size_t)(bh * S_ + q0 + ty + 16 * i) * D_;
#pragma unroll
        for (int j = 0; j < 4; ++j) orow[tx + 16 * j] = c[i][j];
    }
}

// ---------------------------------------------------------------------------
extern "C" void kernel_launch(void* const* d_in, const int* in_sizes, int n_in,
                              void* d_out, int out_size)
{
    (void)in_sizes; (void)n_in; (void)out_size;
    const float* Q    = (const float*)d_in[0];
    const float* K    = (const float*)d_in[1];
    const float* V    = (const float*)d_in[2];
    const int*   mask = (const int*)d_in[3];

    float* out = (float*)d_out;                         // [B,H,S,D]
    float* p   = out + (size_t)B_ * H_ * S_ * D_;       // [B,H,S,S] (e, then p)

    // smem sizes: k1 = (8192+8704+2048)*4 + 256*4 = 76800 B
    //             k2 = (8192+4352+128)*4          = 50688 B
    const int smem1 = (QT * D_ + KT1 * 68 + QT * 16) * 4 + 2 * QT * 4;
    const int smem2 = (QT * D_ + D_ * 68 + QT) * 4;
    cudaFuncSetAttribute(qk_scores_kernel, cudaFuncAttributeMaxDynamicSharedMemorySize, smem1);
    cudaFuncSetAttribute(pv_kernel,        cudaFuncAttributeMaxDynamicSharedMemorySize, smem2);

    dim3 grid(S_ / QT, BH_);
    qk_scores_kernel<<<grid, 256, smem1>>>(Q, K, mask, p);
    pv_kernel<<<grid, 256, smem2>>>(V, p, out);
}

// round 4
// speedup vs baseline: 2.1129x; 2.1129x over previous
#include <cuda_runtime.h>
#include <cuda_bf16.h>
#include <cstdint>
#include <math.h>

#define B_  4
#define H_  12
#define S_  2048
#define D_  64
#define BH_ 48
#define QT  128
#define KC  128

// smem byte offsets (row stride 72 halves = 144 B, ldmatrix conflict-free)
#define OFF_QH 0
#define OFF_QL 18432
#define OFF_KH 36864
#define OFF_KL 55296
#define OFF_VH 73728
#define OFF_VL 92160
#define OFF_KM 110592
#define SMEM_BYTES (110592 + 512)

__device__ float g_l[BH_ * S_];

__device__ __forceinline__ uint32_t smem_u32(const void* p) {
    uint32_t a;
    asm("{ .reg .u64 t; cvta.to.shared.u64 t, %1; cvt.u32.u64 %0, t; }" : "=r"(a) : "l"(p));
    return a;
}

#define LDSM4(R0, R1, R2, R3, A) \
    asm volatile("ldmatrix.sync.aligned.m8n8.x4.shared.b16 {%0,%1,%2,%3}, [%4];" \
        : "=r"(R0), "=r"(R1), "=r"(R2), "=r"(R3) : "r"(A))
#define LDSM4T(R0, R1, R2, R3, A) \
    asm volatile("ldmatrix.sync.aligned.m8n8.x4.trans.shared.b16 {%0,%1,%2,%3}, [%4];" \
        : "=r"(R0), "=r"(R1), "=r"(R2), "=r"(R3) : "r"(A))

__device__ __forceinline__ void mma_bf16(float* c, const uint32_t* a, uint32_t b0, uint32_t b1) {
    asm volatile("mma.sync.aligned.m16n8k16.row.col.f32.bf16.bf16.f32 "
        "{%0,%1,%2,%3}, {%4,%5,%6,%7}, {%8,%9}, {%0,%1,%2,%3};"
        : "+f"(c[0]), "+f"(c[1]), "+f"(c[2]), "+f"(c[3])
        : "r"(a[0]), "r"(a[1]), "r"(a[2]), "r"(a[3]), "r"(b0), "r"(b1));
}

// Split (x,y) into packed bf16x2 hi and lo (residual) words.
__device__ __forceinline__ void split2(float x, float y, uint32_t& hi, uint32_t& lo) {
    __nv_bfloat16 hx = __float2bfloat16(x), hy = __float2bfloat16(y);
    float rx = x - __bfloat162float(hx);
    float ry = y - __bfloat162float(hy);
    __nv_bfloat16 lx = __float2bfloat16(rx), ly = __float2bfloat16(ry);
    hi = (uint32_t)__bfloat16_as_ushort(hx) | ((uint32_t)__bfloat16_as_ushort(hy) << 16);
    lo = (uint32_t)__bfloat16_as_ushort(lx) | ((uint32_t)__bfloat16_as_ushort(ly) << 16);
}

// Load a 128x64 fp32 tile (contiguous) into hi/lo bf16 smem, row stride 144 B.
__device__ __forceinline__ void load_tile(const float4* __restrict__ g,
                                          char* smem, uint32_t hoff, uint32_t loff, int tid)
{
#pragma unroll
    for (int i = 0; i < 8; ++i) {
        int idx = tid + 256 * i;           // 2048 float4 total
        int row = idx >> 4, c4 = idx & 15;
        float4 v = g[idx];
        uint32_t h0, l0, h1, l1;
        split2(v.x, v.y, h0, l0);
        split2(v.z, v.w, h1, l1);
        uint32_t off = row * 144 + c4 * 8;
        *(uint2*)(smem + hoff + off) = make_uint2(h0, h1);
        *(uint2*)(smem + loff + off) = make_uint2(l0, l1);
    }
}

// ---------------------------------------------------------------------------
// Fused attention: per (bh, 128-q tile). QK^T -> exp/mask -> store e (unnorm),
// fragments reused as A of P*V. All GEMMs = mma.sync bf16 with 3-term split.
// ---------------------------------------------------------------------------
__global__ void __launch_bounds__(256, 2)
attn_kernel(const float* __restrict__ Q, const float* __restrict__ K,
            const float* __restrict__ V, const int* __restrict__ mask,
            float* __restrict__ e_out, float* __restrict__ out)
{
    extern __shared__ char sm[];
    const uint32_t smb = smem_u32(sm);
    float* kmf = (float*)(sm + OFF_KM);

    const int tid  = threadIdx.x;
    const int wid  = tid >> 5;
    const int lane = tid & 31;
    const int bh   = blockIdx.y;
    const int b    = bh / H_;
    const int q0   = blockIdx.x * QT;

    // Q tile -> smem (hi/lo)
    load_tile((const float4*)(Q + (size_t)(bh * S_ + q0) * D_), sm, OFF_QH, OFF_QL, tid);
    __syncthreads();

    // Hoist Q A-fragments into registers (persistent): 4 k-steps x 4 regs x hi/lo
    uint32_t qh[4][4], ql[4][4];
    {
        uint32_t row = 16 * wid + (lane & 7) + ((lane >> 3) & 1) * 8;
        uint32_t base = smb + row * 144;
#pragma unroll
        for (int s = 0; s < 4; ++s) {
            uint32_t a = base + (s * 16 + (lane >> 4) * 8) * 2;
            LDSM4(qh[s][0], qh[s][1], qh[s][2], qh[s][3], a + OFF_QH);
            LDSM4(ql[s][0], ql[s][1], ql[s][2], ql[s][3], a + OFF_QL);
        }
    }

    const int rowa = q0 + 16 * wid + (lane >> 2);     // fragment row (and rowa+8)
    const int qm_a = mask[b * S_ + rowa];
    const int qm_b = mask[b * S_ + rowa + 8];

    float o[8][4];
#pragma unroll
    for (int i = 0; i < 8; ++i)
#pragma unroll
        for (int j = 0; j < 4; ++j) o[i][j] = 0.0f;
    float l_a = 0.0f, l_b = 0.0f;

    for (int kc = 0; kc < S_; kc += KC) {
        if (kc) __syncthreads();       // previous chunk's smem reads done
        load_tile((const float4*)(K + (size_t)(bh * S_ + kc) * D_), sm, OFF_KH, OFF_KL, tid);
        load_tile((const float4*)(V + (size_t)(bh * S_ + kc) * D_), sm, OFF_VH, OFF_VL, tid);
        if (tid < KC) kmf[tid] = mask[b * S_ + kc + tid] ? 1.0f : 0.0f;
        __syncthreads();

#pragma unroll 1
        for (int s = 0; s < 8; ++s) {                 // 16 k-cols (2 score tiles) per iter
            float c0[4] = {0.f, 0.f, 0.f, 0.f};
            float c1[4] = {0.f, 0.f, 0.f, 0.f};

            // ---- QK^T for score cols [16s, 16s+16) ----
            {
                uint32_t brow = 16 * s + (lane & 7) + (lane >> 4) * 8;
                uint32_t bb = smb + brow * 144;
#pragma unroll
                for (int d = 0; d < 4; ++d) {
                    uint32_t a = bb + (d * 16 + ((lane >> 3) & 1) * 8) * 2;
                    uint32_t kh0, kh1, kh2, kh3, kl0, kl1, kl2, kl3;
                    LDSM4(kh0, kh1, kh2, kh3, a + OFF_KH);
                    LDSM4(kl0, kl1, kl2, kl3, a + OFF_KL);
                    mma_bf16(c0, qh[d], kh0, kh1);
                    mma_bf16(c0, qh[d], kl0, kl1);
                    mma_bf16(c0, ql[d], kh0, kh1);
                    mma_bf16(c1, qh[d], kh2, kh3);
                    mma_bf16(c1, qh[d], kl2, kl3);
                    mma_bf16(c1, ql[d], kh2, kh3);
                }
            }

            // ---- exp + mask + row-sum partials ----
            const int col0 = 16 * s + 2 * (lane & 3);
            const float m00 = kmf[col0], m01 = kmf[col0 + 1];
            const float m10 = kmf[col0 + 8], m11 = kmf[col0 + 9];
            c0[0] = qm_a ? __expf(c0[0] * 0.125f) * m00 : 1.0f;
            c0[1] = qm_a ? __expf(c0[1] * 0.125f) * m01 : 1.0f;
            c0[2] = qm_b ? __expf(c0[2] * 0.125f) * m00 : 1.0f;
            c0[3] = qm_b ? __expf(c0[3] * 0.125f) * m01 : 1.0f;
            c1[0] = qm_a ? __expf(c1[0] * 0.125f) * m10 : 1.0f;
            c1[1] = qm_a ? __expf(c1[1] * 0.125f) * m11 : 1.0f;
            c1[2] = qm_b ? __expf(c1[2] * 0.125f) * m10 : 1.0f;
            c1[3] = qm_b ? __expf(c1[3] * 0.125f) * m11 : 1.0f;
            l_a += c0[0] + c0[1] + c1[0] + c1[1];
            l_b += c0[2] + c0[3] + c1[2] + c1[3];

            // ---- store unnormalized e (8B per lane = full 32B sectors) ----
            {
                float* base0 = e_out + (size_t)(bh * S_ + rowa) * S_ + kc + col0;
                float* base1 = e_out + (size_t)(bh * S_ + rowa + 8) * S_ + kc + col0;
                *(float2*)(base0)     = make_float2(c0[0], c0[1]);
                *(float2*)(base0 + 8) = make_float2(c1[0], c1[1]);
                *(float2*)(base1)     = make_float2(c0[2], c0[3]);
                *(float2*)(base1 + 8) = make_float2(c1[2], c1[3]);
            }

            // ---- pack P fragments (C-layout == A-layout identity) ----
            uint32_t ah[4], al[4];
            split2(c0[0], c0[1], ah[0], al[0]);
            split2(c0[2], c0[3], ah[1], al[1]);
            split2(c1[0], c1[1], ah[2], al[2]);
            split2(c1[2], c1[3], ah[3], al[3]);

            // ---- O += P * V for k rows [16s, 16s+16) ----
            {
                uint32_t vrow = 16 * s + (lane & 7) + ((lane >> 3) & 1) * 8;
                uint32_t vb = smb + vrow * 144;
#pragma unroll
                for (int d2 = 0; d2 < 4; ++d2) {
                    uint32_t a = vb + (d2 * 16 + (lane >> 4) * 8) * 2;
                    uint32_t vh0, vh1, vh2, vh3, vl0, vl1, vl2, vl3;
                    LDSM4T(vh0, vh1, vh2, vh3, a + OFF_VH);
                    LDSM4T(vl0, vl1, vl2, vl3, a + OFF_VL);
                    mma_bf16(o[2 * d2], ah, vh0, vh1);
                    mma_bf16(o[2 * d2], ah, vl0, vl1);
                    mma_bf16(o[2 * d2], al, vh0, vh1);
                    mma_bf16(o[2 * d2 + 1], ah, vh2, vh3);
                    mma_bf16(o[2 * d2 + 1], ah, vl2, vl3);
                    mma_bf16(o[2 * d2 + 1], al, vh2, vh3);
                }
            }
        }
    }

    // ---- FIX: reduce row-sum partials across the quad (each thread owns only
    //      cols {2m, 2m+1, 2m+8, 2m+9} of every 16; lanes in a quad hold
    //      disjoint column subsets of the SAME row) ----
    l_a += __shfl_xor_sync(0xFFFFFFFFu, l_a, 1);
    l_a += __shfl_xor_sync(0xFFFFFFFFu, l_a, 2);
    l_b += __shfl_xor_sync(0xFFFFFFFFu, l_b, 1);
    l_b += __shfl_xor_sync(0xFFFFFFFFu, l_b, 2);

    // ---- normalize O, write out + row sums ----
    const float ra = 1.0f / l_a;
    const float rb = 1.0f / l_b;
    float* o0 = out + (size_t)(bh * S_ + rowa) * D_;
    float* o1 = out + (size_t)(bh * S_ + rowa + 8) * D_;
#pragma unroll
    for (int nt = 0; nt < 8; ++nt) {
        int col = nt * 8 + 2 * (lane & 3);
        *(float2*)(o0 + col) = make_float2(o[nt][0] * ra, o[nt][1] * ra);
        *(float2*)(o1 + col) = make_float2(o[nt][2] * rb, o[nt][3] * rb);
    }
    if ((lane & 3) == 0) {
        g_l[bh * S_ + rowa] = l_a;
        g_l[bh * S_ + rowa + 8] = l_b;
    }
}

// ---------------------------------------------------------------------------
// Normalize p = e / l (pure bandwidth)
// ---------------------------------------------------------------------------
__global__ void __launch_bounds__(256)
norm_kernel(float4* __restrict__ p)
{
    unsigned long long gi = (unsigned long long)blockIdx.x * 256ull + threadIdx.x;
    int row = (int)(gi >> 9);            // 512 float4 per row
    float rl = 1.0f / g_l[row];
    float4 v = p[gi];
    v.x *= rl; v.y *= rl; v.z *= rl; v.w *= rl;
    p[gi] = v;
}

// ---------------------------------------------------------------------------
extern "C" void kernel_launch(void* const* d_in, const int* in_sizes, int n_in,
                              void* d_out, int out_size)
{
    (void)in_sizes; (void)n_in; (void)out_size;
    const float* Q    = (const float*)d_in[0];
    const float* K    = (const float*)d_in[1];
    const float* V    = (const float*)d_in[2];
    const int*   mask = (const int*)d_in[3];

    float* out = (float*)d_out;                       // [B,H,S,D]
    float* p   = out + (size_t)B_ * H_ * S_ * D_;     // [B,H,S,S]

    cudaFuncSetAttribute(attn_kernel, cudaFuncAttributeMaxDynamicSharedMemorySize, SMEM_BYTES);

    dim3 grid(S_ / QT, BH_);
    attn_kernel<<<grid, 256, SMEM_BYTES>>>(Q, K, V, mask, p, out);

    const unsigned long long total4 = (unsigned long long)B_ * H_ * S_ * S_ / 4ull;
    norm_kernel<<<(unsigned int)(total4 / 256ull), 256>>>((float4*)p);
}

// round 5
// speedup vs baseline: 2.9188x; 1.3814x over previous
#include <cuda_runtime.h>
#include <cuda_fp16.h>
#include <cstdint>
#include <math.h>

#define B_  4
#define H_  12
#define S_  2048
#define D_  64
#define BH_ 48
#define QT  128
#define KC  128

// smem byte offsets (row stride 72 halves = 144 B, ldmatrix conflict-free)
#define OFF_QH 0
#define OFF_QL 18432
#define OFF_KH 36864
#define OFF_VH 55296
#define OFF_KM 73728
#define SMEM_BYTES (73728 + 512)

__device__ float g_l[BH_ * S_];

__device__ __forceinline__ uint32_t smem_u32(const void* p) {
    uint32_t a;
    asm("{ .reg .u64 t; cvta.to.shared.u64 t, %1; cvt.u32.u64 %0, t; }" : "=r"(a) : "l"(p));
    return a;
}

#define LDSM4(R0, R1, R2, R3, A) \
    asm volatile("ldmatrix.sync.aligned.m8n8.x4.shared.b16 {%0,%1,%2,%3}, [%4];" \
        : "=r"(R0), "=r"(R1), "=r"(R2), "=r"(R3) : "r"(A))
#define LDSM4T(R0, R1, R2, R3, A) \
    asm volatile("ldmatrix.sync.aligned.m8n8.x4.trans.shared.b16 {%0,%1,%2,%3}, [%4];" \
        : "=r"(R0), "=r"(R1), "=r"(R2), "=r"(R3) : "r"(A))

__device__ __forceinline__ void mma_f16(float* c, const uint32_t* a, uint32_t b0, uint32_t b1) {
    asm volatile("mma.sync.aligned.m16n8k16.row.col.f32.f16.f16.f32 "
        "{%0,%1,%2,%3}, {%4,%5,%6,%7}, {%8,%9}, {%0,%1,%2,%3};"
        : "+f"(c[0]), "+f"(c[1]), "+f"(c[2]), "+f"(c[3])
        : "r"(a[0]), "r"(a[1]), "r"(a[2]), "r"(a[3]), "r"(b0), "r"(b1));
}

__device__ __forceinline__ uint32_t packh2(__half a, __half b) {
    return (uint32_t)__half_as_ushort(a) | ((uint32_t)__half_as_ushort(b) << 16);
}

// fp16 hi/lo split of (x,y) into packed h16x2 words.
__device__ __forceinline__ void split2h(float x, float y, uint32_t& hi, uint32_t& lo) {
    __half hx = __float2half_rn(x), hy = __float2half_rn(y);
    float rx = x - __half2float(hx);
    float ry = y - __half2float(hy);
    hi = packh2(hx, hy);
    lo = packh2(__float2half_rn(rx), __float2half_rn(ry));
}

// 128x64 fp32 tile -> fp16 hi+lo smem (row stride 144 B). 256 threads.
__device__ __forceinline__ void load_tile_hilo(const float4* __restrict__ g,
                                               char* smem, uint32_t hoff, uint32_t loff, int tid)
{
#pragma unroll
    for (int i = 0; i < 8; ++i) {
        int idx = tid + 256 * i;
        int row = idx >> 4, c4 = idx & 15;
        float4 v = g[idx];
        uint32_t h0, l0, h1, l1;
        split2h(v.x, v.y, h0, l0);
        split2h(v.z, v.w, h1, l1);
        uint32_t off = row * 144 + c4 * 8;
        *(uint2*)(smem + hoff + off) = make_uint2(h0, h1);
        *(uint2*)(smem + loff + off) = make_uint2(l0, l1);
    }
}

// 128x64 fp32 tile -> fp16 (hi only) smem. 256 threads.
__device__ __forceinline__ void load_tile_hi(const float4* __restrict__ g,
                                             char* smem, uint32_t hoff, int tid)
{
#pragma unroll
    for (int i = 0; i < 8; ++i) {
        int idx = tid + 256 * i;
        int row = idx >> 4, c4 = idx & 15;
        float4 v = g[idx];
        uint32_t h0 = packh2(__float2half_rn(v.x), __float2half_rn(v.y));
        uint32_t h1 = packh2(__float2half_rn(v.z), __float2half_rn(v.w));
        *(uint2*)(smem + hoff + row * 144 + c4 * 8) = make_uint2(h0, h1);
    }
}

// ---------------------------------------------------------------------------
// Fused attention: QK^T (fp16 2-term: (qh+ql)*kh) -> exp/mask -> store e,
// O += (eh+el)*vh. mma.sync m16n8k16 fp16, fp32 accumulate.
// ---------------------------------------------------------------------------
__global__ void __launch_bounds__(256, 2)
attn_kernel(const float* __restrict__ Q, const float* __restrict__ K,
            const float* __restrict__ V, const int* __restrict__ mask,
            float* __restrict__ e_out, float* __restrict__ out)
{
    extern __shared__ char sm[];
    const uint32_t smb = smem_u32(sm);
    float* kmf = (float*)(sm + OFF_KM);

    const int tid  = threadIdx.x;
    const int wid  = tid >> 5;
    const int lane = tid & 31;
    const int bh   = blockIdx.y;
    const int b    = bh / H_;
    const int q0   = blockIdx.x * QT;

    load_tile_hilo((const float4*)(Q + (size_t)(bh * S_ + q0) * D_), sm, OFF_QH, OFF_QL, tid);
    __syncthreads();

    // Hoist Q A-fragments (hi + lo) into registers
    uint32_t qh[4][4], ql[4][4];
    {
        uint32_t row = 16 * wid + (lane & 7) + ((lane >> 3) & 1) * 8;
        uint32_t base = smb + row * 144;
#pragma unroll
        for (int s = 0; s < 4; ++s) {
            uint32_t a = base + (s * 16 + (lane >> 4) * 8) * 2;
            LDSM4(qh[s][0], qh[s][1], qh[s][2], qh[s][3], a + OFF_QH);
            LDSM4(ql[s][0], ql[s][1], ql[s][2], ql[s][3], a + OFF_QL);
        }
    }

    const int rowa = q0 + 16 * wid + (lane >> 2);
    const int qm_a = mask[b * S_ + rowa];
    const int qm_b = mask[b * S_ + rowa + 8];
    const float qs_a = qm_a ? 0.125f : 0.0f;    // exp(0)=1 handles dead rows
    const float qs_b = qm_b ? 0.125f : 0.0f;

    float o[8][4];
#pragma unroll
    for (int i = 0; i < 8; ++i)
#pragma unroll
        for (int j = 0; j < 4; ++j) o[i][j] = 0.0f;
    float l_a = 0.0f, l_b = 0.0f;

    for (int kc = 0; kc < S_; kc += KC) {
        if (kc) __syncthreads();
        load_tile_hi((const float4*)(K + (size_t)(bh * S_ + kc) * D_), sm, OFF_KH, tid);
        load_tile_hi((const float4*)(V + (size_t)(bh * S_ + kc) * D_), sm, OFF_VH, tid);
        if (tid < KC) kmf[tid] = mask[b * S_ + kc + tid] ? 1.0f : 0.0f;
        __syncthreads();

#pragma unroll 1
        for (int s = 0; s < 8; ++s) {
            float c0[4] = {0.f, 0.f, 0.f, 0.f};
            float c1[4] = {0.f, 0.f, 0.f, 0.f};

            // ---- QK^T: (qh + ql) * kh ----
            {
                uint32_t brow = 16 * s + (lane & 7) + (lane >> 4) * 8;
                uint32_t bb = smb + brow * 144 + OFF_KH;
#pragma unroll
                for (int d = 0; d < 4; ++d) {
                    uint32_t a = bb + (d * 16 + ((lane >> 3) & 1) * 8) * 2;
                    uint32_t kh0, kh1, kh2, kh3;
                    LDSM4(kh0, kh1, kh2, kh3, a);
                    mma_f16(c0, qh[d], kh0, kh1);
                    mma_f16(c0, ql[d], kh0, kh1);
                    mma_f16(c1, qh[d], kh2, kh3);
                    mma_f16(c1, ql[d], kh2, kh3);
                }
            }

            // ---- exp + mask + row-sum partials ----
            const int col0 = 16 * s + 2 * (lane & 3);
            const float m00 = qm_a ? kmf[col0]     : 1.0f;
            const float m01 = qm_a ? kmf[col0 + 1] : 1.0f;
            const float m10 = qm_a ? kmf[col0 + 8] : 1.0f;
            const float m11 = qm_a ? kmf[col0 + 9] : 1.0f;
            const float n00 = qm_b ? kmf[col0]     : 1.0f;
            const float n01 = qm_b ? kmf[col0 + 1] : 1.0f;
            const float n10 = qm_b ? kmf[col0 + 8] : 1.0f;
            const float n11 = qm_b ? kmf[col0 + 9] : 1.0f;
            c0[0] = __expf(c0[0] * qs_a) * m00;
            c0[1] = __expf(c0[1] * qs_a) * m01;
            c0[2] = __expf(c0[2] * qs_b) * n00;
            c0[3] = __expf(c0[3] * qs_b) * n01;
            c1[0] = __expf(c1[0] * qs_a) * m10;
            c1[1] = __expf(c1[1] * qs_a) * m11;
            c1[2] = __expf(c1[2] * qs_b) * n10;
            c1[3] = __expf(c1[3] * qs_b) * n11;
            l_a += c0[0] + c0[1] + c1[0] + c1[1];
            l_b += c0[2] + c0[3] + c1[2] + c1[3];

            // ---- store unnormalized e ----
            {
                float* base0 = e_out + (size_t)(bh * S_ + rowa) * S_ + kc + col0;
                float* base1 = e_out + (size_t)(bh * S_ + rowa + 8) * S_ + kc + col0;
                *(float2*)(base0)     = make_float2(c0[0], c0[1]);
                *(float2*)(base0 + 8) = make_float2(c1[0], c1[1]);
                *(float2*)(base1)     = make_float2(c0[2], c0[3]);
                *(float2*)(base1 + 8) = make_float2(c1[2], c1[3]);
            }

            // ---- pack E fragments (fp16 hi + lo; C-layout == A-layout) ----
            uint32_t eh[4], el[4];
            split2h(c0[0], c0[1], eh[0], el[0]);
            split2h(c0[2], c0[3], eh[1], el[1]);
            split2h(c1[0], c1[1], eh[2], el[2]);
            split2h(c1[2], c1[3], eh[3], el[3]);

            // ---- O += (eh + el) * vh ----
            {
                uint32_t vrow = 16 * s + (lane & 7) + ((lane >> 3) & 1) * 8;
                uint32_t vb = smb + vrow * 144 + OFF_VH;
#pragma unroll
                for (int d2 = 0; d2 < 4; ++d2) {
                    uint32_t a = vb + (d2 * 16 + (lane >> 4) * 8) * 2;
                    uint32_t vh0, vh1, vh2, vh3;
                    LDSM4T(vh0, vh1, vh2, vh3, a);
                    mma_f16(o[2 * d2], eh, vh0, vh1);
                    mma_f16(o[2 * d2], el, vh0, vh1);
                    mma_f16(o[2 * d2 + 1], eh, vh2, vh3);
                    mma_f16(o[2 * d2 + 1], el, vh2, vh3);
                }
            }
        }
    }

    // Quad reduction of row sums (lanes in a quad hold disjoint cols of same row)
    l_a += __shfl_xor_sync(0xFFFFFFFFu, l_a, 1);
    l_a += __shfl_xor_sync(0xFFFFFFFFu, l_a, 2);
    l_b += __shfl_xor_sync(0xFFFFFFFFu, l_b, 1);
    l_b += __shfl_xor_sync(0xFFFFFFFFu, l_b, 2);

    const float ra = 1.0f / l_a;
    const float rb = 1.0f / l_b;
    float* o0 = out + (size_t)(bh * S_ + rowa) * D_;
    float* o1 = out + (size_t)(bh * S_ + rowa + 8) * D_;
#pragma unroll
    for (int nt = 0; nt < 8; ++nt) {
        int col = nt * 8 + 2 * (lane & 3);
        *(float2*)(o0 + col) = make_float2(o[nt][0] * ra, o[nt][1] * ra);
        *(float2*)(o1 + col) = make_float2(o[nt][2] * rb, o[nt][3] * rb);
    }
    if ((lane & 3) == 0) {
        g_l[bh * S_ + rowa] = l_a;
        g_l[bh * S_ + rowa + 8] = l_b;
    }
}

// ---------------------------------------------------------------------------
// Normalize p = e / l. One block per q-row (512 float4), streaming hints.
// ---------------------------------------------------------------------------
__global__ void __launch_bounds__(256)
norm_kernel(float4* __restrict__ p)
{
    const int row = blockIdx.x;
    const float rl = 1.0f / g_l[row];
    float4* base = p + (size_t)row * 512 + threadIdx.x;
    float4 v0 = __ldcs(base);
    float4 v1 = __ldcs(base + 256);
    v0.x *= rl; v0.y *= rl; v0.z *= rl; v0.w *= rl;
    v1.x *= rl; v1.y *= rl; v1.z *= rl; v1.w *= rl;
    __stcs(base, v0);
    __stcs(base + 256, v1);
}

// ---------------------------------------------------------------------------
extern "C" void kernel_launch(void* const* d_in, const int* in_sizes, int n_in,
                              void* d_out, int out_size)
{
    (void)in_sizes; (void)n_in; (void)out_size;
    const float* Q    = (const float*)d_in[0];
    const float* K    = (const float*)d_in[1];
    const float* V    = (const float*)d_in[2];
    const int*   mask = (const int*)d_in[3];

    float* out = (float*)d_out;                       // [B,H,S,D]
    float* p   = out + (size_t)B_ * H_ * S_ * D_;     // [B,H,S,S]

    cudaFuncSetAttribute(attn_kernel, cudaFuncAttributeMaxDynamicSharedMemorySize, SMEM_BYTES);

    dim3 grid(S_ / QT, BH_);
    attn_kernel<<<grid, 256, SMEM_BYTES>>>(Q, K, V, mask, p, out);

    norm_kernel<<<BH_ * S_, 256>>>((float4*)p);
}

// round 6
// speedup vs baseline: 3.4662x; 1.1875x over previous
#include <cuda_runtime.h>
#include <cuda_fp16.h>
#include <cstdint>
#include <math.h>

#define B_  4
#define H_  12
#define S_  2048
#define D_  64
#define BH_ 48
#define QT  128
#define KC  128

// smem byte offsets (row stride 72 halves = 144 B, ldmatrix conflict-free)
#define OFF_QH 0
#define OFF_QL 18432
#define OFF_KH 36864
#define OFF_VH 55296
#define OFF_KM 73728
#define SMEM_BYTES (73728 + 512)

__device__ float  g_l[BH_ * S_];
__device__ __half g_e[(size_t)BH_ * S_ * S_];   // fp16 unnormalized e scratch (402 MB)

__device__ __forceinline__ uint32_t smem_u32(const void* p) {
    uint32_t a;
    asm("{ .reg .u64 t; cvta.to.shared.u64 t, %1; cvt.u32.u64 %0, t; }" : "=r"(a) : "l"(p));
    return a;
}

#define LDSM4(R0, R1, R2, R3, A) \
    asm volatile("ldmatrix.sync.aligned.m8n8.x4.shared.b16 {%0,%1,%2,%3}, [%4];" \
        : "=r"(R0), "=r"(R1), "=r"(R2), "=r"(R3) : "r"(A))
#define LDSM4T(R0, R1, R2, R3, A) \
    asm volatile("ldmatrix.sync.aligned.m8n8.x4.trans.shared.b16 {%0,%1,%2,%3}, [%4];" \
        : "=r"(R0), "=r"(R1), "=r"(R2), "=r"(R3) : "r"(A))

__device__ __forceinline__ void mma_f16(float* c, const uint32_t* a, uint32_t b0, uint32_t b1) {
    asm volatile("mma.sync.aligned.m16n8k16.row.col.f32.f16.f16.f32 "
        "{%0,%1,%2,%3}, {%4,%5,%6,%7}, {%8,%9}, {%0,%1,%2,%3};"
        : "+f"(c[0]), "+f"(c[1]), "+f"(c[2]), "+f"(c[3])
        : "r"(a[0]), "r"(a[1]), "r"(a[2]), "r"(a[3]), "r"(b0), "r"(b1));
}

__device__ __forceinline__ uint32_t packh2(__half a, __half b) {
    return (uint32_t)__half_as_ushort(a) | ((uint32_t)__half_as_ushort(b) << 16);
}

// fp16 hi/lo split of (x,y) into packed h16x2 words.
__device__ __forceinline__ void split2h(float x, float y, uint32_t& hi, uint32_t& lo) {
    __half hx = __float2half_rn(x), hy = __float2half_rn(y);
    float rx = x - __half2float(hx);
    float ry = y - __half2float(hy);
    hi = packh2(hx, hy);
    lo = packh2(__float2half_rn(rx), __float2half_rn(ry));
}

// 128x64 fp32 tile -> fp16 hi+lo smem (row stride 144 B). 256 threads.
__device__ __forceinline__ void load_tile_hilo(const float4* __restrict__ g,
                                               char* smem, uint32_t hoff, uint32_t loff, int tid)
{
#pragma unroll
    for (int i = 0; i < 8; ++i) {
        int idx = tid + 256 * i;
        int row = idx >> 4, c4 = idx & 15;
        float4 v = g[idx];
        uint32_t h0, l0, h1, l1;
        split2h(v.x, v.y, h0, l0);
        split2h(v.z, v.w, h1, l1);
        uint32_t off = row * 144 + c4 * 8;
        *(uint2*)(smem + hoff + off) = make_uint2(h0, h1);
        *(uint2*)(smem + loff + off) = make_uint2(l0, l1);
    }
}

// 128x64 fp32 tile -> fp16 (hi only) smem. 256 threads.
__device__ __forceinline__ void load_tile_hi(const float4* __restrict__ g,
                                             char* smem, uint32_t hoff, int tid)
{
#pragma unroll
    for (int i = 0; i < 8; ++i) {
        int idx = tid + 256 * i;
        int row = idx >> 4, c4 = idx & 15;
        float4 v = g[idx];
        uint32_t h0 = packh2(__float2half_rn(v.x), __float2half_rn(v.y));
        uint32_t h1 = packh2(__float2half_rn(v.z), __float2half_rn(v.w));
        *(uint2*)(smem + hoff + row * 144 + c4 * 8) = make_uint2(h0, h1);
    }
}

// ---------------------------------------------------------------------------
// Fused attention: QK^T (fp16 2-term: (qh+ql)*kh) -> exp/mask -> fp16 e to
// scratch, O += eh*vh (single term). mma.sync m16n8k16 fp16, fp32 accumulate.
// ---------------------------------------------------------------------------
__global__ void __launch_bounds__(256, 2)
attn_kernel(const float* __restrict__ Q, const float* __restrict__ K,
            const float* __restrict__ V, const int* __restrict__ mask,
            float* __restrict__ out)
{
    extern __shared__ char sm[];
    const uint32_t smb = smem_u32(sm);
    float* kmf = (float*)(sm + OFF_KM);

    const int tid  = threadIdx.x;
    const int wid  = tid >> 5;
    const int lane = tid & 31;
    const int bh   = blockIdx.y;
    const int b    = bh / H_;
    const int q0   = blockIdx.x * QT;

    load_tile_hilo((const float4*)(Q + (size_t)(bh * S_ + q0) * D_), sm, OFF_QH, OFF_QL, tid);
    __syncthreads();

    // Hoist Q A-fragments (hi + lo) into registers
    uint32_t qh[4][4], ql[4][4];
    {
        uint32_t row = 16 * wid + (lane & 7) + ((lane >> 3) & 1) * 8;
        uint32_t base = smb + row * 144;
#pragma unroll
        for (int s = 0; s < 4; ++s) {
            uint32_t a = base + (s * 16 + (lane >> 4) * 8) * 2;
            LDSM4(qh[s][0], qh[s][1], qh[s][2], qh[s][3], a + OFF_QH);
            LDSM4(ql[s][0], ql[s][1], ql[s][2], ql[s][3], a + OFF_QL);
        }
    }

    const int rowa = q0 + 16 * wid + (lane >> 2);
    const int qm_a = mask[b * S_ + rowa];
    const int qm_b = mask[b * S_ + rowa + 8];
    const float qs_a = qm_a ? 0.125f : 0.0f;    // exp(0)=1 handles dead rows
    const float qs_b = qm_b ? 0.125f : 0.0f;

    float o[8][4];
#pragma unroll
    for (int i = 0; i < 8; ++i)
#pragma unroll
        for (int j = 0; j < 4; ++j) o[i][j] = 0.0f;
    float l_a = 0.0f, l_b = 0.0f;

    for (int kc = 0; kc < S_; kc += KC) {
        if (kc) __syncthreads();
        load_tile_hi((const float4*)(K + (size_t)(bh * S_ + kc) * D_), sm, OFF_KH, tid);
        load_tile_hi((const float4*)(V + (size_t)(bh * S_ + kc) * D_), sm, OFF_VH, tid);
        if (tid < KC) kmf[tid] = mask[b * S_ + kc + tid] ? 1.0f : 0.0f;
        __syncthreads();

#pragma unroll 1
        for (int s = 0; s < 8; ++s) {
            float c0[4] = {0.f, 0.f, 0.f, 0.f};
            float c1[4] = {0.f, 0.f, 0.f, 0.f};

            // ---- QK^T: (qh + ql) * kh ----
            {
                uint32_t brow = 16 * s + (lane & 7) + (lane >> 4) * 8;
                uint32_t bb = smb + brow * 144 + OFF_KH;
#pragma unroll
                for (int d = 0; d < 4; ++d) {
                    uint32_t a = bb + (d * 16 + ((lane >> 3) & 1) * 8) * 2;
                    uint32_t kh0, kh1, kh2, kh3;
                    LDSM4(kh0, kh1, kh2, kh3, a);
                    mma_f16(c0, qh[d], kh0, kh1);
                    mma_f16(c0, ql[d], kh0, kh1);
                    mma_f16(c1, qh[d], kh2, kh3);
                    mma_f16(c1, ql[d], kh2, kh3);
                }
            }

            // ---- exp + mask + row-sum partials ----
            const int col0 = 16 * s + 2 * (lane & 3);
            const float m00 = qm_a ? kmf[col0]     : 1.0f;
            const float m01 = qm_a ? kmf[col0 + 1] : 1.0f;
            const float m10 = qm_a ? kmf[col0 + 8] : 1.0f;
            const float m11 = qm_a ? kmf[col0 + 9] : 1.0f;
            const float n00 = qm_b ? kmf[col0]     : 1.0f;
            const float n01 = qm_b ? kmf[col0 + 1] : 1.0f;
            const float n10 = qm_b ? kmf[col0 + 8] : 1.0f;
            const float n11 = qm_b ? kmf[col0 + 9] : 1.0f;
            c0[0] = __expf(c0[0] * qs_a) * m00;
            c0[1] = __expf(c0[1] * qs_a) * m01;
            c0[2] = __expf(c0[2] * qs_b) * n00;
            c0[3] = __expf(c0[3] * qs_b) * n01;
            c1[0] = __expf(c1[0] * qs_a) * m10;
            c1[1] = __expf(c1[1] * qs_a) * m11;
            c1[2] = __expf(c1[2] * qs_b) * n10;
            c1[3] = __expf(c1[3] * qs_b) * n11;
            l_a += c0[0] + c0[1] + c1[0] + c1[1];
            l_b += c0[2] + c0[3] + c1[2] + c1[3];

            // ---- pack E fragments (fp16; C-layout == A-layout) ----
            uint32_t eh[4];
            eh[0] = packh2(__float2half_rn(c0[0]), __float2half_rn(c0[1]));
            eh[1] = packh2(__float2half_rn(c0[2]), __float2half_rn(c0[3]));
            eh[2] = packh2(__float2half_rn(c1[0]), __float2half_rn(c1[1]));
            eh[3] = packh2(__float2half_rn(c1[2]), __float2half_rn(c1[3]));

            // ---- store fp16 e to scratch (quad covers full 32B sectors) ----
            {
                __half* base0 = g_e + (size_t)(bh * S_ + rowa) * S_ + kc + col0;
                __half* base1 = g_e + (size_t)(bh * S_ + rowa + 8) * S_ + kc + col0;
                *(uint32_t*)(base0)     = eh[0];
                *(uint32_t*)(base0 + 8) = eh[2];
                *(uint32_t*)(base1)     = eh[1];
                *(uint32_t*)(base1 + 8) = eh[3];
            }

            // ---- O += eh * vh (single-term PV) ----
            {
                uint32_t vrow = 16 * s + (lane & 7) + ((lane >> 3) & 1) * 8;
                uint32_t vb = smb + vrow * 144 + OFF_VH;
#pragma unroll
                for (int d2 = 0; d2 < 4; ++d2) {
                    uint32_t a = vb + (d2 * 16 + (lane >> 4) * 8) * 2;
                    uint32_t vh0, vh1, vh2, vh3;
                    LDSM4T(vh0, vh1, vh2, vh3, a);
                    mma_f16(o[2 * d2], eh, vh0, vh1);
                    mma_f16(o[2 * d2 + 1], eh, vh2, vh3);
                }
            }
        }
    }

    // Quad reduction of row sums (lanes in a quad hold disjoint cols of same row)
    l_a += __shfl_xor_sync(0xFFFFFFFFu, l_a, 1);
    l_a += __shfl_xor_sync(0xFFFFFFFFu, l_a, 2);
    l_b += __shfl_xor_sync(0xFFFFFFFFu, l_b, 1);
    l_b += __shfl_xor_sync(0xFFFFFFFFu, l_b, 2);

    const float ra = 1.0f / l_a;
    const float rb = 1.0f / l_b;
    float* o0 = out + (size_t)(bh * S_ + rowa) * D_;
    float* o1 = out + (size_t)(bh * S_ + rowa + 8) * D_;
#pragma unroll
    for (int nt = 0; nt < 8; ++nt) {
        int col = nt * 8 + 2 * (lane & 3);
        *(float2*)(o0 + col) = make_float2(o[nt][0] * ra, o[nt][1] * ra);
        *(float2*)(o1 + col) = make_float2(o[nt][2] * rb, o[nt][3] * rb);
    }
    if ((lane & 3) == 0) {
        g_l[bh * S_ + rowa] = l_a;
        g_l[bh * S_ + rowa + 8] = l_b;
    }
}

// ---------------------------------------------------------------------------
// Normalize: p(fp32) = e(fp16) / l. One block per q-row; thread reads 8 halves
// (uint4), writes 2 float4. Streaming hints (no reuse).
// ---------------------------------------------------------------------------
__global__ void __launch_bounds__(256)
norm_kernel(float4* __restrict__ p)
{
    const int row = blockIdx.x;
    const float rl = 1.0f / g_l[row];
    const uint4* src = (const uint4*)(g_e + (size_t)row * S_) + threadIdx.x;
    uint4 ew = __ldcs(src);
    const __half2* h2 = (const __half2*)&ew;
    float4 v0, v1;
    float2 a0 = __half22float2(h2[0]);
    float2 a1 = __half22float2(h2[1]);
    float2 a2 = __half22float2(h2[2]);
    float2 a3 = __half22float2(h2[3]);
    v0.x = a0.x * rl; v0.y = a0.y * rl; v0.z = a1.x * rl; v0.w = a1.y * rl;
    v1.x = a2.x * rl; v1.y = a2.y * rl; v1.z = a3.x * rl; v1.w = a3.y * rl;
    float4* dst = p + (size_t)row * (S_ / 4) + threadIdx.x * 2;
    __stcs(dst,     v0);
    __stcs(dst + 1, v1);
}

// ---------------------------------------------------------------------------
extern "C" void kernel_launch(void* const* d_in, const int* in_sizes, int n_in,
                              void* d_out, int out_size)
{
    (void)in_sizes; (void)n_in; (void)out_size;
    const float* Q    = (const float*)d_in[0];
    const float* K    = (const float*)d_in[1];
    const float* V    = (const float*)d_in[2];
    const int*   mask = (const int*)d_in[3];

    float* out = (float*)d_out;                       // [B,H,S,D]
    float* p   = out + (size_t)B_ * H_ * S_ * D_;     // [B,H,S,S]

    cudaFuncSetAttribute(attn_kernel, cudaFuncAttributeMaxDynamicSharedMemorySize, SMEM_BYTES);

    dim3 grid(S_ / QT, BH_);
    attn_kernel<<<grid, 256, SMEM_BYTES>>>(Q, K, V, mask, out);

    norm_kernel<<<BH_ * S_, 256>>>((float4*)p);
}